// round 2
// baseline (speedup 1.0000x reference)
#include <cuda_runtime.h>

// CompressKV: y[b,m,h,d] = (sum_k x[b, m*16+k, h, d]*w[k] + sum_k pe[k,d]*w[k]) / 32
// x (4,16384,8,128) f32, w (32) f32, pe (32,128) f32, y (4,1023,8,128) f32.
//
// Rolling-window: each warp owns TM consecutive m outputs. Rows are streamed
// once; each 16-row group contributes to two windows (k=16..31 of the older,
// k=0..15 of the newer). 20 LDG.128 per output instead of 32.

#define CB 4
#define CN 16384
#define CH 8
#define CD 128
#define CK 32
#define CSTRIDE 16
#define CM 1023          // (16384 - 32)/16 + 1
#define TM 4             // outputs per warp-strip
#define WARPS 4          // warps (strips) per block
#define STRIPS 256       // ceil(CM / TM)

__global__ __launch_bounds__(128, 6)
void compresskv_kernel(const float4* __restrict__ x,
                       const float*  __restrict__ w,
                       const float4* __restrict__ pe,
                       float4*       __restrict__ y)
{
    const int d4    = threadIdx.x & 31;      // float4 lane within 128-float row
    const int wid   = threadIdx.x >> 5;
    const int strip = blockIdx.x * WARPS + wid;   // 0..255 exactly
    const int m0    = strip * TM;
    const int h     = blockIdx.y;
    const int b     = blockIdx.z;

    // weights -> registers (reused across TM+1 groups)
    float wk[CK];
#pragma unroll
    for (int k = 0; k < CK; ++k) wk[k] = __ldg(&w[k]);

    // bias[d] = sum_k pe[k][d] * w[k]   (pe is 16 KB, L1/L2 resident)
    float bx = 0.f, by = 0.f, bz = 0.f, bw = 0.f;
#pragma unroll
    for (int k = 0; k < CK; ++k) {
        float4 p = __ldg(&pe[k * (CD / 4) + d4]);
        bx = fmaf(wk[k], p.x, bx);
        by = fmaf(wk[k], p.y, by);
        bz = fmaf(wk[k], p.z, bz);
        bw = fmaf(wk[k], p.w, bw);
    }

    const int ROW4 = CH * (CD / 4);          // 256 float4 between consecutive n (and m in y)
    const float4* xb = x + ((size_t)b * CN * CH + h) * (CD / 4) + d4;
    float4*       yb = y + ((size_t)b * CM * CH + h) * (CD / 4) + d4;

    // accA: older window (gets k=16..31 this group); accB: newer (gets k=0..15)
    float aAx = 0.f, aAy = 0.f, aAz = 0.f, aAw = 0.f;
    float aBx = 0.f, aBy = 0.f, aBz = 0.f, aBw = 0.f;

#pragma unroll
    for (int g = 0; g <= TM; ++g) {
        const int mg = m0 + g;               // group index == newer window index
        if (mg <= 1023) {                    // rows 16*mg .. 16*mg+15 in range
            const float4* xp = xb + (size_t)(mg * CSTRIDE) * ROW4;
#pragma unroll
            for (int r = 0; r < CSTRIDE; ++r) {
                float4 v = __ldg(&xp[(size_t)r * ROW4]);
                if (g > 0) {                 // compile-time: g is unrolled constant
                    aAx = fmaf(wk[CSTRIDE + r], v.x, aAx);
                    aAy = fmaf(wk[CSTRIDE + r], v.y, aAy);
                    aAz = fmaf(wk[CSTRIDE + r], v.z, aAz);
                    aAw = fmaf(wk[CSTRIDE + r], v.w, aAw);
                }
                if (g < TM) {
                    aBx = fmaf(wk[r], v.x, aBx);
                    aBy = fmaf(wk[r], v.y, aBy);
                    aBz = fmaf(wk[r], v.z, aBz);
                    aBw = fmaf(wk[r], v.w, aBw);
                }
            }
        }
        if (g > 0) {
            const int m = mg - 1;            // window m is now complete
            if (m < CM) {
                float4 o;
                o.x = (aAx + bx) * 0.03125f;
                o.y = (aAy + by) * 0.03125f;
                o.z = (aAz + bz) * 0.03125f;
                o.w = (aAw + bw) * 0.03125f;
                yb[(size_t)m * ROW4] = o;
            }
        }
        // shift: newer becomes older
        aAx = aBx; aAy = aBy; aAz = aBz; aAw = aBw;
        aBx = 0.f; aBy = 0.f; aBz = 0.f; aBw = 0.f;
    }
}

extern "C" void kernel_launch(void* const* d_in, const int* in_sizes, int n_in,
                              void* d_out, int out_size)
{
    const float4* x  = (const float4*)d_in[0];
    const float*  w  = (const float*) d_in[1];
    const float4* pe = (const float4*)d_in[2];
    float4*       y  = (float4*)d_out;

    dim3 grid(STRIPS / WARPS, CH, CB);       // (64, 8, 4) = 2048 blocks
    dim3 block(WARPS * 32);                  // 128 threads
    compresskv_kernel<<<grid, block>>>(x, w, pe, y);
}

// round 3
// speedup vs baseline: 1.2689x; 1.2689x over previous
#include <cuda_runtime.h>

// CompressKV: y[b,m,h,d] = (sum_k x[b, m*16+k, h, d]*w[k] + sum_k pe[k,d]*w[k]) / 32
// x (4,16384,8,128) f32, w (32) f32, pe (32,128) f32, y (4,1023,8,128) f32.
//
// R1 mapping (1.0x DRAM traffic via intra-CTA L1 dedup of the 2x window
// overlap) + smem weights/bias to cut regs 128 -> ~64 and double occupancy.

#define CB 4
#define CN 16384
#define CH 8
#define CD 128
#define CK 32
#define CSTRIDE 16
#define CM 1023          // (16384 - 32)/16 + 1
#define MCHUNK 8
#define ROW4 (CH * (CD / 4))   // 256 float4 between consecutive n

__global__ __launch_bounds__(256, 4)
void compresskv_kernel(const float4* __restrict__ x,
                       const float*  __restrict__ w,
                       const float4* __restrict__ pe,
                       float4*       __restrict__ y)
{
    __shared__ float  sw[CK];
    __shared__ float4 sbias[CD / 4];

    const int tid = threadIdx.x;
    const int d4  = tid & 31;            // float4 lane within 128-float row
    const int j   = tid >> 5;            // local m within chunk

    if (tid < CK) sw[tid] = w[tid];
    __syncthreads();

    // one warp computes bias[d] = sum_k pe[k][d]*w[k] for the whole block
    if (tid < CD / 4) {
        float bx = 0.f, by = 0.f, bz = 0.f, bw = 0.f;
#pragma unroll
        for (int k = 0; k < CK; ++k) {
            float4 p  = __ldg(&pe[k * (CD / 4) + tid]);
            float  wv = sw[k];
            bx = fmaf(wv, p.x, bx);
            by = fmaf(wv, p.y, by);
            bz = fmaf(wv, p.z, bz);
            bw = fmaf(wv, p.w, bw);
        }
        float4 o; o.x = bx; o.y = by; o.z = bz; o.w = bw;
        sbias[tid] = o;
    }
    __syncthreads();

    const int m = blockIdx.x * MCHUNK + j;
    const int h = blockIdx.y;
    const int b = blockIdx.z;

    if (m < CM) {
        const float4* xp = x + ((size_t)((b * CN + m * CSTRIDE) * CH + h)) * (CD / 4) + d4;

        float ax = 0.f, ay = 0.f, az = 0.f, aw = 0.f;
#pragma unroll
        for (int k = 0; k < CK; ++k) {
            float4 v  = __ldg(&xp[(size_t)k * ROW4]);
            float  wv = sw[k];
            ax = fmaf(wv, v.x, ax);
            ay = fmaf(wv, v.y, ay);
            az = fmaf(wv, v.z, az);
            aw = fmaf(wv, v.w, aw);
        }

        float4 bias = sbias[d4];
        float4 out;
        out.x = (ax + bias.x) * 0.03125f;
        out.y = (ay + bias.y) * 0.03125f;
        out.z = (az + bias.z) * 0.03125f;
        out.w = (aw + bias.w) * 0.03125f;
        y[((size_t)((b * CM + m) * CH + h)) * (CD / 4) + d4] = out;
    }
}

extern "C" void kernel_launch(void* const* d_in, const int* in_sizes, int n_in,
                              void* d_out, int out_size)
{
    const float4* x  = (const float4*)d_in[0];
    const float*  w  = (const float*) d_in[1];
    const float4* pe = (const float4*)d_in[2];
    float4*       y  = (float4*)d_out;

    dim3 grid((CM + MCHUNK - 1) / MCHUNK, CH, CB);   // (128, 8, 4)
    dim3 block(256);
    compresskv_kernel<<<grid, block>>>(x, w, pe, y);
}